// round 7
// baseline (speedup 1.0000x reference)
#include <cuda_runtime.h>
#include <cuda_bf16.h>
#include <math.h>
#include <stdint.h>

// ---------------------------------------------------------------------------
// Net_23553600651528: [conv1 fused into conv2 block] -> conv2 (bf16 mma,
// 32 M-rows/warp sharing B frags, scalar-LDS A, 3 blocks/SM) + relu +
// maxpool (bf16 out) -> fc1 (bf16 mma, K-split) -> [fc2+sigmoid ->
// 10-qubit statevector -> <Y> -> log_softmax].  B = 2048.
// ---------------------------------------------------------------------------

#define BATCH 2048

// scratch (__device__ globals; allocation-free rule)
__device__ __nv_bfloat16 g_poolh[BATCH * 9216]; // pooled conv2 bf16, [b][quad*64+oc]
__device__ float g_fc1[BATCH * 128];            // fc1 output
__device__ float g_part[8 * BATCH * 128];       // fc1 K-split partials
__device__ uint4 g_wfragb[18 * 4 * 32];         // conv2 weights, bf16 B-fragments
__device__ float g_fc1wp[128 * 9216];           // fc1 weights fp32, K permuted
__device__ uint4 g_fc1wfrag[576 * 8 * 32];      // fc1 weights, bf16 B-fragments

__device__ __forceinline__ uint32_t packbf(float lo, float hi) {
    __nv_bfloat162 h2 = __floats2bfloat162_rn(lo, hi);   // .x=lo -> low 16 bits
    return *reinterpret_cast<uint32_t*>(&h2);
}

__device__ __forceinline__ void mma_bf16(float& c0, float& c1, float& c2, float& c3,
                                         uint32_t a0, uint32_t a1, uint32_t a2, uint32_t a3,
                                         uint32_t b0, uint32_t b1) {
    asm volatile("mma.sync.aligned.m16n8k16.row.col.f32.bf16.bf16.f32 "
                 "{%0,%1,%2,%3}, {%4,%5,%6,%7}, {%8,%9}, {%0,%1,%2,%3};"
                 : "+f"(c0), "+f"(c1), "+f"(c2), "+f"(c3)
                 : "r"(a0), "r"(a1), "r"(a2), "r"(a3), "r"(b0), "r"(b1));
}

// ---------------------------------------------------------------------------
// prep: conv2 weights -> bf16 B-fragments (m16n8k16).  k = r*32+ic, step s:
// r=s>>1, icb=(s&1)*16.  uint4 = (b0,b1) pairs for oc-frags 2p, 2p+1.
// ---------------------------------------------------------------------------
__global__ void prep_wfrag_kernel(const float* __restrict__ w2)
{
    const int s = blockIdx.x;          // 0..17
    const int tid = threadIdx.x;       // 0..127
    const int p = tid >> 5;
    const int lane = tid & 31;
    const int g = lane >> 2, c = lane & 3;
    const int r = s >> 1;
    const int icb = (s & 1) * 16;
    const int oc_a = (2 * p) * 8 + g;
    const int oc_b = oc_a + 8;
    const int i00 = icb + 2 * c, i01 = i00 + 1;
    const int i10 = i00 + 8,     i11 = i10 + 1;
#define WV(ic, oc) w2[(oc) * 288 + (ic) * 9 + r]
    uint4 v;
    v.x = packbf(WV(i00, oc_a), WV(i01, oc_a));
    v.y = packbf(WV(i10, oc_a), WV(i11, oc_a));
    v.z = packbf(WV(i00, oc_b), WV(i01, oc_b));
    v.w = packbf(WV(i10, oc_b), WV(i11, oc_b));
#undef WV
    g_wfragb[(s * 4 + p) * 32 + lane] = v;
}

// ---------------------------------------------------------------------------
// prep: fc1 weights permuted to k' = quad*64 + oc  (fp32 intermediate)
// ---------------------------------------------------------------------------
__global__ void prep_fc1w_kernel(const float* __restrict__ fc1_w)
{
    const int i = blockIdx.x * 256 + threadIdx.x;
    const int n = i / 9216;
    const int kp = i - n * 9216;
    const int quad = kp >> 6;
    const int oc = kp & 63;
    g_fc1wp[i] = fc1_w[n * 9216 + oc * 144 + quad];
}

// ---------------------------------------------------------------------------
// prep: fc1 permuted weights -> bf16 B-fragments.  576 k-steps, 16 n-frags
// packed as 8 uint4 pairs.
// ---------------------------------------------------------------------------
__global__ void prep_fc1frag_kernel()
{
    const int s = blockIdx.x;          // 0..575
    const int tid = threadIdx.x;       // 0..255
    const int p = tid >> 5;            // n-frag pair 0..7
    const int lane = tid & 31;
    const int g = lane >> 2, c = lane & 3;
    const int k0 = s * 16;
    const int n_a = (2 * p) * 8 + g;
    const int n_b = n_a + 8;
    const float2 wa0 = *(const float2*)(g_fc1wp + (size_t)n_a * 9216 + k0 + 2 * c);
    const float2 wa1 = *(const float2*)(g_fc1wp + (size_t)n_a * 9216 + k0 + 2 * c + 8);
    const float2 wb0 = *(const float2*)(g_fc1wp + (size_t)n_b * 9216 + k0 + 2 * c);
    const float2 wb1 = *(const float2*)(g_fc1wp + (size_t)n_b * 9216 + k0 + 2 * c + 8);
    uint4 v;
    v.x = packbf(wa0.x, wa0.y);
    v.y = packbf(wa1.x, wa1.y);
    v.z = packbf(wb0.x, wb0.y);
    v.w = packbf(wb1.x, wb1.y);
    g_fc1wfrag[(s * 8 + p) * 32 + lane] = v;
}

// ---------------------------------------------------------------------------
// fused conv1+conv2: one block per batch element, 256 threads / 8 warps,
// __launch_bounds__(256,3) -> 3 blocks/SM (smem 50.6KB x 3 = 152KB).
//   conv1+relu -> smem bf16 position-major, stride 34 bf16 (17 words).
//   conv2: warp-tile = 32 M rows (8 quads) -> 2 A-frags per B-frag load
//   (halves dominant B LDG traffic); 18 warp-tiles, warp w does wt = w, w+8,
//   (w+16 if w<2).  Epilogue: maxpool via shfl_xor, bias+relu, bf16 store.
// ---------------------------------------------------------------------------
__global__ void __launch_bounds__(256, 3) conv12_kernel(const float* __restrict__ x,
                                                        const float* __restrict__ w1,
                                                        const float* __restrict__ b1,
                                                        const float* __restrict__ b2)
{
    extern __shared__ char smem[];
    __nv_bfloat16* sIn = (__nv_bfloat16*)smem;               // 676*34 bf16 = 45968 B
    float* sx  = (float*)(smem + 45968);                     // 784 f
    float* sw1 = (float*)(smem + 45968 + 3136);              // 288 f
    float* sb1 = (float*)(smem + 45968 + 3136 + 1152);       // 32 f
    float* sb2 = (float*)(smem + 45968 + 3136 + 1152 + 128); // 64 f

    const int b = blockIdx.x;
    const int tid = threadIdx.x;
    const int w = tid >> 5;
    const int lane = tid & 31;

    // ---- stage inputs ----
    for (int i = tid; i < 784; i += 256) sx[i] = x[b * 784 + i];
    for (int i = tid; i < 288; i += 256) sw1[i] = w1[i];
    if (tid < 32) sb1[tid] = b1[tid];
    for (int i = tid; i < 64; i += 256) sb2[i] = b2[i];
    __syncthreads();

    // ---- conv1 + relu -> sIn (bf16, 34 bf16 / position) ----
    for (int p = tid; p < 676; p += 256) {
        const int oy = p / 26, ox = p % 26;
        float in[9];
#pragma unroll
        for (int kh = 0; kh < 3; kh++)
#pragma unroll
            for (int kw = 0; kw < 3; kw++)
                in[kh * 3 + kw] = sx[(oy + kh) * 28 + ox + kw];
        uint32_t* dst = (uint32_t*)(sIn + p * 34);
#pragma unroll 4
        for (int oc2 = 0; oc2 < 16; oc2++) {
            float va = sb1[2 * oc2], vb = sb1[2 * oc2 + 1];
            const float* wa = sw1 + (2 * oc2) * 9;
#pragma unroll
            for (int j = 0; j < 9; j++) { va += wa[j] * in[j]; vb += wa[9 + j] * in[j]; }
            dst[oc2] = packbf(fmaxf(va, 0.0f), fmaxf(vb, 0.0f));
        }
    }
    __syncthreads();

    // ---- conv2 GEMM: 18 warp-tiles of 32 rows (2 A-frags each) ----
    const uint32_t* sIn32 = (const uint32_t*)sIn;   // 17 words per position
    const int c = lane & 3;
    const int rl0 = lane >> 2;
    __nv_bfloat16* outB = g_poolh + (size_t)b * 9216;

    for (int wt = w; wt < 18; wt += 8) {
        const int qb = wt * 8;         // 8 quads = 32 rows per warp-tile

        // per-lane word offsets for the two A frags (16 rows each)
        int wA0, wA1, wE0, wE1;
        {
            int quad = qb + (rl0 >> 2), e = rl0 & 3;
            int qy = quad / 12, qx = quad - qy * 12;
            wA0 = ((2 * qy + (e >> 1)) * 26 + 2 * qx + (e & 1)) * 17 + c;
            quad = qb + ((rl0 + 8) >> 2); e = rl0 & 3;
            qy = quad / 12; qx = quad - qy * 12;
            wA1 = ((2 * qy + (e >> 1)) * 26 + 2 * qx + (e & 1)) * 17 + c;
            quad = qb + 4 + (rl0 >> 2); e = rl0 & 3;
            qy = quad / 12; qx = quad - qy * 12;
            wE0 = ((2 * qy + (e >> 1)) * 26 + 2 * qx + (e & 1)) * 17 + c;
            quad = qb + 4 + ((rl0 + 8) >> 2); e = rl0 & 3;
            qy = quad / 12; qx = quad - qy * 12;
            wE1 = ((2 * qy + (e >> 1)) * 26 + 2 * qx + (e & 1)) * 17 + c;
        }

        float accA[8][4], accE[8][4];
#pragma unroll
        for (int n = 0; n < 8; n++) {
            accA[n][0] = 0.f; accA[n][1] = 0.f; accA[n][2] = 0.f; accA[n][3] = 0.f;
            accE[n][0] = 0.f; accE[n][1] = 0.f; accE[n][2] = 0.f; accE[n][3] = 0.f;
        }

#pragma unroll
        for (int r = 0; r < 9; r++) {
            const int khw17 = ((r / 3) * 26 + (r % 3)) * 17;
#pragma unroll
            for (int h = 0; h < 2; h++) {            // ic halves (icb = h*16)
                const int base = khw17 + h * 8;
                const uint32_t a0 = sIn32[wA0 + base];
                const uint32_t a1 = sIn32[wA1 + base];
                const uint32_t a2 = sIn32[wA0 + base + 4];
                const uint32_t a3 = sIn32[wA1 + base + 4];
                const uint32_t e0 = sIn32[wE0 + base];
                const uint32_t e1 = sIn32[wE1 + base];
                const uint32_t e2 = sIn32[wE0 + base + 4];
                const uint32_t e3 = sIn32[wE1 + base + 4];
                const uint4* wf = g_wfragb + (r * 2 + h) * 128;
#pragma unroll
                for (int p4 = 0; p4 < 4; p4++) {
                    const uint4 bq = wf[p4 * 32 + lane];
                    mma_bf16(accA[2 * p4][0], accA[2 * p4][1], accA[2 * p4][2], accA[2 * p4][3],
                             a0, a1, a2, a3, bq.x, bq.y);
                    mma_bf16(accA[2 * p4 + 1][0], accA[2 * p4 + 1][1],
                             accA[2 * p4 + 1][2], accA[2 * p4 + 1][3],
                             a0, a1, a2, a3, bq.z, bq.w);
                    mma_bf16(accE[2 * p4][0], accE[2 * p4][1], accE[2 * p4][2], accE[2 * p4][3],
                             e0, e1, e2, e3, bq.x, bq.y);
                    mma_bf16(accE[2 * p4 + 1][0], accE[2 * p4 + 1][1],
                             accE[2 * p4 + 1][2], accE[2 * p4 + 1][3],
                             e0, e1, e2, e3, bq.z, bq.w);
                }
            }
        }

        // epilogue: maxpool via shfl_xor, bias+relu, bf16 store
        const int hh = lane >> 4;
        const int rr = lane & 3;
        const bool writer = ((lane & 12) == 0);
#pragma unroll
        for (int f = 0; f < 2; f++) {
            const int qf = qb + f * 4;
#pragma unroll
            for (int n = 0; n < 8; n++) {
                float v0 = f ? accE[n][0] : accA[n][0];
                float v1 = f ? accE[n][1] : accA[n][1];
                float v2 = f ? accE[n][2] : accA[n][2];
                float v3 = f ? accE[n][3] : accA[n][3];
#pragma unroll
                for (int d = 4; d <= 8; d <<= 1) {
                    v0 = fmaxf(v0, __shfl_xor_sync(0xffffffffu, v0, d));
                    v1 = fmaxf(v1, __shfl_xor_sync(0xffffffffu, v1, d));
                    v2 = fmaxf(v2, __shfl_xor_sync(0xffffffffu, v2, d));
                    v3 = fmaxf(v3, __shfl_xor_sync(0xffffffffu, v3, d));
                }
                if (writer) {
                    const int oc = n * 8 + 2 * rr;
                    const float ba = sb2[oc], bb = sb2[oc + 1];
                    *(uint32_t*)(outB + (qf + hh) * 64 + oc) =
                        packbf(fmaxf(v0 + ba, 0.f), fmaxf(v1 + bb, 0.f));
                    *(uint32_t*)(outB + (qf + 2 + hh) * 64 + oc) =
                        packbf(fmaxf(v2 + ba, 0.f), fmaxf(v3 + bb, 0.f));
                }
            }
        }
    }
}

// ---------------------------------------------------------------------------
// fc1 bf16 tensor-core with K-split: grid (16 Mblocks, 8 ksplits), 256 thr.
// ---------------------------------------------------------------------------
__global__ void __launch_bounds__(256) fc1_part_kernel()
{
    const int tid = threadIdx.x;
    const int w = tid >> 5;
    const int lane = tid & 31;
    const int Mb = blockIdx.x;         // 0..15
    const int ks = blockIdx.y;         // 0..7
    const int m0 = Mb * 128 + w * 16;
    const int g = lane >> 2, c = lane & 3;

    float acc[16][4];
#pragma unroll
    for (int f = 0; f < 16; f++) {
        acc[f][0] = 0.f; acc[f][1] = 0.f; acc[f][2] = 0.f; acc[f][3] = 0.f;
    }

    const __nv_bfloat16* A0 = g_poolh + (size_t)(m0 + g) * 9216;
    const __nv_bfloat16* A1 = g_poolh + (size_t)(m0 + g + 8) * 9216;

    for (int step = 0; step < 72; step++) {
        const int k0 = ks * 1152 + step * 16;
        const uint32_t a0 = *(const uint32_t*)(A0 + k0 + 2 * c);
        const uint32_t a1 = *(const uint32_t*)(A1 + k0 + 2 * c);
        const uint32_t a2 = *(const uint32_t*)(A0 + k0 + 2 * c + 8);
        const uint32_t a3 = *(const uint32_t*)(A1 + k0 + 2 * c + 8);
        const uint4* wf = g_fc1wfrag + (size_t)(ks * 72 + step) * 256;
#pragma unroll
        for (int p4 = 0; p4 < 8; p4++) {
            const uint4 bq = wf[p4 * 32 + lane];
            mma_bf16(acc[2 * p4][0], acc[2 * p4][1], acc[2 * p4][2], acc[2 * p4][3],
                     a0, a1, a2, a3, bq.x, bq.y);
            mma_bf16(acc[2 * p4 + 1][0], acc[2 * p4 + 1][1],
                     acc[2 * p4 + 1][2], acc[2 * p4 + 1][3],
                     a0, a1, a2, a3, bq.z, bq.w);
        }
    }

    float* dst = g_part + (size_t)ks * BATCH * 128;
#pragma unroll
    for (int f = 0; f < 16; f++) {
        const int n0 = f * 8 + 2 * c;
        *(float2*)(dst + (size_t)(m0 + g) * 128 + n0) = make_float2(acc[f][0], acc[f][1]);
        *(float2*)(dst + (size_t)(m0 + g + 8) * 128 + n0) = make_float2(acc[f][2], acc[f][3]);
    }
}

__global__ void fc1_reduce_kernel(const float* __restrict__ bias)
{
    const int i = blockIdx.x * 256 + threadIdx.x;
    float s = 0.0f;
#pragma unroll
    for (int ks = 0; ks < 8; ks++) s += g_part[(size_t)ks * BATCH * 128 + i];
    s += bias[i & 127];
    g_fc1[i] = fmaxf(s, 0.0f);
}

// ---------------------------------------------------------------------------
// quantum kernel; wire w <-> bit (9-w).  Single-pass <Y_k> reduction.
// ---------------------------------------------------------------------------
__device__ __forceinline__ float2 cmul(float2 a, float2 b) {
    return make_float2(a.x * b.x - a.y * b.y, a.x * b.y + a.y * b.x);
}
__device__ __forceinline__ float2 cadd(float2 a, float2 b) {
    return make_float2(a.x + b.x, a.y + b.y);
}

__global__ void qsim_kernel(const float* __restrict__ fc2w,
                            const float* __restrict__ fc2b,
                            const float* __restrict__ theta0,
                            const float* __restrict__ theta_rz,
                            const float* __restrict__ theta_ps,
                            const float* __restrict__ rot_p,
                            float* __restrict__ out)
{
    __shared__ float sh[128];
    __shared__ float sang[10];
    __shared__ float2 svec[10][2];
    __shared__ float2 psi[1024];
    __shared__ float sredk[8][10];
    __shared__ float sev[10];

    const int b = blockIdx.x;
    const int tid = threadIdx.x;
    const int wid = tid >> 5, lane = tid & 31;

    if (tid < 128) sh[tid] = g_fc1[(size_t)b * 128 + tid];
    __syncthreads();

    if (tid < 10) {
        float z = fc2b[tid];
        const float4* sh4 = (const float4*)sh;
        const float4* wr4 = (const float4*)(fc2w + tid * 128);
        for (int k = 0; k < 32; k++) {
            const float4 hv = sh4[k], wv = wr4[k];
            z += hv.x * wv.x + hv.y * wv.y + hv.z * wv.z + hv.w * wv.w;
        }
        const float a = 6.2831853071795864f / (1.0f + expf(-z));
        sang[tid] = a;

        float alpha = theta0[tid] + a;
        if (tid == 1) alpha += a;
        if (tid == 5) alpha -= 0.78539816339745f;
        const float c = cosf(0.5f * alpha);
        const float s = sinf(0.5f * alpha);
        float2 v0 = make_float2(c, 0.0f);
        float2 v1 = make_float2(0.0f, -s);

        if (tid == 2) {
            const float cy = cosf(0.5f * a), sy = sinf(0.5f * a);
            v0 = make_float2(cy * c, sy * s);
            v1 = make_float2(sy * c, -cy * s);
        } else if (tid == 3) {
            const float2 e = make_float2(cosf(0.5f * a), -sinf(0.5f * a));
            v0 = cmul(v0, e);
            v1 = cmul(v1, make_float2(e.x, -e.y));
        } else if (tid == 4) {
            v1 = make_float2(s, 0.0f);
        } else if (tid == 5) {
            const float r = 0.70710678118654752f;
            v1 = make_float2(s * r, -s * r);
        } else if (tid == 6) {
            const float t = theta_rz[0];
            const float2 e = make_float2(cosf(0.5f * t), -sinf(0.5f * t));
            v0 = cmul(v0, e);
            v1 = cmul(v1, make_float2(e.x, -e.y));
        } else if (tid == 7) {
            const float h0 = 0.5f * (c - s), h1 = 0.5f * (c + s);
            v0 = make_float2(h0, h0);
            v1 = make_float2(h1, -h1);
        }
        svec[tid][0] = v0;
        svec[tid][1] = v1;
    }
    __syncthreads();

    for (int i = tid; i < 1024; i += 256) {
        float2 p = svec[0][(i >> 9) & 1];
#pragma unroll
        for (int k = 1; k < 10; k++)
            p = cmul(p, svec[k][(i >> (9 - k)) & 1]);
        if (i & 512) p = make_float2(p.y, -p.x);
        psi[i] = p;
    }
    __syncthreads();

    for (int p = tid; p < 512; p += 256) {
        const int i0 = ((p & ~1) << 1) | (p & 1);
        if (i0 & 64) {
            const int i1 = i0 | 2;
            const float2 t0 = psi[i0], t1 = psi[i1];
            psi[i0] = make_float2(t1.y, -t1.x);
            psi[i1] = make_float2(-t0.y, t0.x);
        }
    }
    __syncthreads();

    for (int i = tid; i < 1024; i += 256) {
        if ((i & 192) == 128) {
            const int j = i ^ 192;
            const float2 t = psi[i]; psi[i] = psi[j]; psi[j] = t;
        }
    }
    __syncthreads();

    for (int i = tid; i < 1024; i += 256) {
        if ((i & 32) && ((i & 24) == 16)) {
            const int j = i ^ 24;
            const float2 t = psi[i]; psi[i] = psi[j]; psi[j] = t;
        }
    }
    __syncthreads();

    for (int p = tid; p < 512; p += 256) {
        if ((p & 18) == 18) {
            const int j = p | 512;
            const float2 t = psi[p]; psi[p] = psi[j]; psi[j] = t;
        }
    }
    __syncthreads();

    {
        const float tps = theta_ps[0];
        const float a7 = sang[7];
        const float2 e8 = make_float2(cosf(tps), sinf(tps));
        const float2 e7 = make_float2(cosf(a7), sinf(a7));
        for (int i = tid; i < 1024; i += 256) {
            float2 v = psi[i];
            if (i & 2) v = cmul(v, e8);
            if (i & 4) v = cmul(v, e7);
            psi[i] = v;
        }
    }
    __syncthreads();

    {
        const float phi = rot_p[0], th = rot_p[1], om = rot_p[2];
        const float c = cosf(0.5f * th), s = sinf(0.5f * th);
        const float hs = 0.5f * (phi + om), hd = 0.5f * (phi - om);
        const float2 m00 = make_float2(c * cosf(hs), -c * sinf(hs));
        const float2 m01 = make_float2(-s * cosf(hd), -s * sinf(hd));
        const float2 m10 = make_float2(s * cosf(hd), -s * sinf(hd));
        const float2 m11 = make_float2(c * cosf(hs), c * sinf(hs));
        for (int p = tid; p < 512; p += 256) {
            const int lo = p & 31;
            const int i0 = ((p - lo) << 1) | lo;
            const int i1 = i0 | 32;
            const float2 t0 = psi[i0], t1 = psi[i1];
            psi[i0] = cadd(cmul(m00, t0), cmul(m01, t1));
            psi[i1] = cadd(cmul(m10, t0), cmul(m11, t1));
        }
    }
    __syncthreads();

    {
        const float phi = sang[6], th = sang[7], om = sang[8];
        const float c = cosf(0.5f * th), s = sinf(0.5f * th);
        const float hs = 0.5f * (phi + om), hd = 0.5f * (phi - om);
        const float2 m00 = make_float2(c * cosf(hs), -c * sinf(hs));
        const float2 m01 = make_float2(-s * cosf(hd), -s * sinf(hd));
        const float2 m10 = make_float2(s * cosf(hd), -s * sinf(hd));
        const float2 m11 = make_float2(c * cosf(hs), c * sinf(hs));
        for (int p = tid; p < 512; p += 256) {
            const int lo = p & 15;
            const int i0 = ((p - lo) << 1) | lo;
            const int i1 = i0 | 16;
            const float2 t0 = psi[i0], t1 = psi[i1];
            psi[i0] = cadd(cmul(m00, t0), cmul(m01, t1));
            psi[i1] = cadd(cmul(m10, t0), cmul(m11, t1));
        }
    }
    __syncthreads();

    // single-pass expectations
    float ev[10];
#pragma unroll
    for (int k = 0; k < 10; k++) ev[k] = 0.0f;
#pragma unroll
    for (int ii = 0; ii < 4; ii++) {
        const int i = tid + ii * 256;
        const float2 a0 = psi[i];
#pragma unroll
        for (int k = 0; k < 10; k++) {
            const int bit = 512 >> k;
            if (!(i & bit)) {
                const float2 a1 = psi[i | bit];
                ev[k] += a0.x * a1.y - a0.y * a1.x;
            }
        }
    }
#pragma unroll
    for (int k = 0; k < 10; k++) {
#pragma unroll
        for (int off = 16; off > 0; off >>= 1)
            ev[k] += __shfl_down_sync(0xffffffffu, ev[k], off);
    }
    if (lane == 0) {
#pragma unroll
        for (int k = 0; k < 10; k++) sredk[wid][k] = ev[k];
    }
    __syncthreads();
    if (tid < 10) {
        float s = 0.0f;
#pragma unroll
        for (int w = 0; w < 8; w++) s += sredk[w][tid];
        sev[tid] = 2.0f * s;
    }
    __syncthreads();

    if (tid == 0) {
        float m = sev[0];
#pragma unroll
        for (int k = 1; k < 10; k++) m = fmaxf(m, sev[k]);
        float ssum = 0.0f;
#pragma unroll
        for (int k = 0; k < 10; k++) ssum += expf(sev[k] - m);
        const float l = logf(ssum);
#pragma unroll
        for (int k = 0; k < 10; k++)
            out[(size_t)b * 10 + k] = sev[k] - m - l;
    }
}

// ---------------------------------------------------------------------------
// launch
// ---------------------------------------------------------------------------
extern "C" void kernel_launch(void* const* d_in, const int* in_sizes, int n_in,
                              void* d_out, int out_size)
{
    const float* x        = (const float*)d_in[0];
    const float* conv1_w  = (const float*)d_in[1];
    const float* conv1_b  = (const float*)d_in[2];
    const float* conv2_w  = (const float*)d_in[3];
    const float* conv2_b  = (const float*)d_in[4];
    const float* fc1_w    = (const float*)d_in[5];
    const float* fc1_b    = (const float*)d_in[6];
    const float* fc2_w    = (const float*)d_in[7];
    const float* fc2_b    = (const float*)d_in[8];
    const float* theta0   = (const float*)d_in[9];
    const float* theta_rz = (const float*)d_in[10];
    const float* theta_ps = (const float*)d_in[11];
    const float* rot_p    = (const float*)d_in[12];
    float* out = (float*)d_out;

    // sIn 45968 + sx 3136 + sw1 1152 + sb1 128 + sb2 256 = 50640 B
    const int conv_smem = 50640;
    cudaFuncSetAttribute(conv12_kernel, cudaFuncAttributeMaxDynamicSharedMemorySize,
                         conv_smem);

    prep_wfrag_kernel<<<18, 128>>>(conv2_w);
    prep_fc1w_kernel<<<(128 * 9216) / 256, 256>>>(fc1_w);
    prep_fc1frag_kernel<<<576, 256>>>();
    conv12_kernel<<<BATCH, 256, conv_smem>>>(x, conv1_w, conv1_b, conv2_b);
    fc1_part_kernel<<<dim3(16, 8), 256>>>();
    fc1_reduce_kernel<<<(BATCH * 128) / 256, 256>>>(fc1_b);
    qsim_kernel<<<BATCH, 256>>>(fc2_w, fc2_b, theta0, theta_rz, theta_ps, rot_p, out);
}

// round 8
// speedup vs baseline: 1.7840x; 1.7840x over previous
#include <cuda_runtime.h>
#include <cuda_bf16.h>
#include <math.h>
#include <stdint.h>

// ---------------------------------------------------------------------------
// Net_23553600651528: [conv1 fused into conv2 block] -> conv2 (bf16 mma,
// scalar-LDS A, 16 M-rows/warp, natural occupancy) + relu + maxpool (bf16)
// -> fc1 (bf16 mma, K-split) -> [K-split reduce fused into qsim: fc2+sigmoid
// -> 10-qubit statevector -> <Y> -> log_softmax].  B = 2048.
// ---------------------------------------------------------------------------

#define BATCH 2048

// scratch (__device__ globals; allocation-free rule)
__device__ __nv_bfloat16 g_poolh[BATCH * 9216]; // pooled conv2 bf16, [b][quad*64+oc]
__device__ float g_part[8 * BATCH * 128];       // fc1 K-split partials
__device__ uint4 g_wfragb[18 * 4 * 32];         // conv2 weights, bf16 B-fragments
__device__ float g_fc1wp[128 * 9216];           // fc1 weights fp32, K permuted
__device__ uint4 g_fc1wfrag[576 * 8 * 32];      // fc1 weights, bf16 B-fragments

__device__ __forceinline__ uint32_t packbf(float lo, float hi) {
    __nv_bfloat162 h2 = __floats2bfloat162_rn(lo, hi);   // .x=lo -> low 16 bits
    return *reinterpret_cast<uint32_t*>(&h2);
}

__device__ __forceinline__ void mma_bf16(float& c0, float& c1, float& c2, float& c3,
                                         uint32_t a0, uint32_t a1, uint32_t a2, uint32_t a3,
                                         uint32_t b0, uint32_t b1) {
    asm volatile("mma.sync.aligned.m16n8k16.row.col.f32.bf16.bf16.f32 "
                 "{%0,%1,%2,%3}, {%4,%5,%6,%7}, {%8,%9}, {%0,%1,%2,%3};"
                 : "+f"(c0), "+f"(c1), "+f"(c2), "+f"(c3)
                 : "r"(a0), "r"(a1), "r"(a2), "r"(a3), "r"(b0), "r"(b1));
}

// ---------------------------------------------------------------------------
// prep: conv2 weights -> bf16 B-fragments (m16n8k16).  k = r*32+ic, step s:
// r=s>>1, icb=(s&1)*16.  uint4 = (b0,b1) pairs for oc-frags 2p, 2p+1.
// ---------------------------------------------------------------------------
__global__ void prep_wfrag_kernel(const float* __restrict__ w2)
{
    const int s = blockIdx.x;          // 0..17
    const int tid = threadIdx.x;       // 0..127
    const int p = tid >> 5;
    const int lane = tid & 31;
    const int g = lane >> 2, c = lane & 3;
    const int r = s >> 1;
    const int icb = (s & 1) * 16;
    const int oc_a = (2 * p) * 8 + g;
    const int oc_b = oc_a + 8;
    const int i00 = icb + 2 * c, i01 = i00 + 1;
    const int i10 = i00 + 8,     i11 = i10 + 1;
#define WV(ic, oc) w2[(oc) * 288 + (ic) * 9 + r]
    uint4 v;
    v.x = packbf(WV(i00, oc_a), WV(i01, oc_a));
    v.y = packbf(WV(i10, oc_a), WV(i11, oc_a));
    v.z = packbf(WV(i00, oc_b), WV(i01, oc_b));
    v.w = packbf(WV(i10, oc_b), WV(i11, oc_b));
#undef WV
    g_wfragb[(s * 4 + p) * 32 + lane] = v;
}

// ---------------------------------------------------------------------------
// prep: fc1 weights permuted to k' = quad*64 + oc  (fp32 intermediate)
// ---------------------------------------------------------------------------
__global__ void prep_fc1w_kernel(const float* __restrict__ fc1_w)
{
    const int i = blockIdx.x * 256 + threadIdx.x;
    const int n = i / 9216;
    const int kp = i - n * 9216;
    const int quad = kp >> 6;
    const int oc = kp & 63;
    g_fc1wp[i] = fc1_w[n * 9216 + oc * 144 + quad];
}

// ---------------------------------------------------------------------------
// prep: fc1 permuted weights -> bf16 B-fragments.  576 k-steps, 16 n-frags
// packed as 8 uint4 pairs.
// ---------------------------------------------------------------------------
__global__ void prep_fc1frag_kernel()
{
    const int s = blockIdx.x;          // 0..575
    const int tid = threadIdx.x;       // 0..255
    const int p = tid >> 5;            // n-frag pair 0..7
    const int lane = tid & 31;
    const int g = lane >> 2, c = lane & 3;
    const int k0 = s * 16;
    const int n_a = (2 * p) * 8 + g;
    const int n_b = n_a + 8;
    const float2 wa0 = *(const float2*)(g_fc1wp + (size_t)n_a * 9216 + k0 + 2 * c);
    const float2 wa1 = *(const float2*)(g_fc1wp + (size_t)n_a * 9216 + k0 + 2 * c + 8);
    const float2 wb0 = *(const float2*)(g_fc1wp + (size_t)n_b * 9216 + k0 + 2 * c);
    const float2 wb1 = *(const float2*)(g_fc1wp + (size_t)n_b * 9216 + k0 + 2 * c + 8);
    uint4 v;
    v.x = packbf(wa0.x, wa0.y);
    v.y = packbf(wa1.x, wa1.y);
    v.z = packbf(wb0.x, wb0.y);
    v.w = packbf(wb1.x, wb1.y);
    g_fc1wfrag[(s * 8 + p) * 32 + lane] = v;
}

// ---------------------------------------------------------------------------
// fused conv1+conv2: one block per batch element, 256 threads / 8 warps,
// natural occupancy (~66 regs -> 3 blocks/SM; smem 50.6KB x 3 = 152KB).
//   conv1+relu -> smem bf16 position-major, stride 34 bf16 (17 words).
//   conv2: warp-tile = 16 M rows (4 quads), N=64; A via 4 scalar LDS.32 per
//   k-step, B frags via LDG (L1-hot); 36 warp-tiles over 5 rounds.
//   epilogue: 2x2 maxpool via shfl_xor, bias+relu, bf16 store [quad][oc].
// ---------------------------------------------------------------------------
__global__ void __launch_bounds__(256) conv12_kernel(const float* __restrict__ x,
                                                     const float* __restrict__ w1,
                                                     const float* __restrict__ b1,
                                                     const float* __restrict__ b2)
{
    extern __shared__ char smem[];
    __nv_bfloat16* sIn = (__nv_bfloat16*)smem;               // 676*34 bf16 = 45968 B
    float* sx  = (float*)(smem + 45968);                     // 784 f
    float* sw1 = (float*)(smem + 45968 + 3136);              // 288 f
    float* sb1 = (float*)(smem + 45968 + 3136 + 1152);       // 32 f
    float* sb2 = (float*)(smem + 45968 + 3136 + 1152 + 128); // 64 f

    const int b = blockIdx.x;
    const int tid = threadIdx.x;
    const int w = tid >> 5;
    const int lane = tid & 31;

    // ---- stage inputs ----
    for (int i = tid; i < 784; i += 256) sx[i] = x[b * 784 + i];
    for (int i = tid; i < 288; i += 256) sw1[i] = w1[i];
    if (tid < 32) sb1[tid] = b1[tid];
    for (int i = tid; i < 64; i += 256) sb2[i] = b2[i];
    __syncthreads();

    // ---- conv1 + relu -> sIn (bf16, 34 bf16 / position) ----
    for (int p = tid; p < 676; p += 256) {
        const int oy = p / 26, ox = p % 26;
        float in[9];
#pragma unroll
        for (int kh = 0; kh < 3; kh++)
#pragma unroll
            for (int kw = 0; kw < 3; kw++)
                in[kh * 3 + kw] = sx[(oy + kh) * 28 + ox + kw];
        uint32_t* dst = (uint32_t*)(sIn + p * 34);
#pragma unroll 4
        for (int oc2 = 0; oc2 < 16; oc2++) {
            float va = sb1[2 * oc2], vb = sb1[2 * oc2 + 1];
            const float* wa = sw1 + (2 * oc2) * 9;
#pragma unroll
            for (int j = 0; j < 9; j++) { va += wa[j] * in[j]; vb += wa[9 + j] * in[j]; }
            dst[oc2] = packbf(fmaxf(va, 0.0f), fmaxf(vb, 0.0f));
        }
    }
    __syncthreads();

    // ---- conv2 GEMM: 36 warp-tiles of 16 rows over 5 rounds ----
    const uint32_t* sIn32 = (const uint32_t*)sIn;   // 17 words per position
    const int c = lane & 3;
    const int rl0 = lane >> 2;
    __nv_bfloat16* outB = g_poolh + (size_t)b * 9216;

    for (int t = 0; t < 5; t++) {
        if (t == 4 && w >= 4) break;      // 576 = 4*128 + 64 rows
        int off0, off1;
        {
            const int qb = t * 32 + w * 4;
            int rl = rl0;
            int quad = qb + (rl >> 2), e = rl & 3;
            int qy = quad / 12, qx = quad - qy * 12;
            off0 = (2 * qy + (e >> 1)) * 26 + 2 * qx + (e & 1);
            rl = rl0 + 8;
            quad = qb + (rl >> 2); e = rl & 3;
            qy = quad / 12; qx = quad - qy * 12;
            off1 = (2 * qy + (e >> 1)) * 26 + 2 * qx + (e & 1);
        }
        const int w0 = off0 * 17 + c;
        const int w1b = off1 * 17 + c;

        float acc[8][4];
#pragma unroll
        for (int n = 0; n < 8; n++) {
            acc[n][0] = 0.f; acc[n][1] = 0.f; acc[n][2] = 0.f; acc[n][3] = 0.f;
        }

#pragma unroll
        for (int r = 0; r < 9; r++) {
            const int khw17 = ((r / 3) * 26 + (r % 3)) * 17;
#pragma unroll
            for (int h = 0; h < 2; h++) {            // ic halves (icb = h*16)
                const int base = khw17 + h * 8;
                const uint32_t a0 = sIn32[w0 + base];
                const uint32_t a1 = sIn32[w1b + base];
                const uint32_t a2 = sIn32[w0 + base + 4];
                const uint32_t a3 = sIn32[w1b + base + 4];
                const uint4* wf = g_wfragb + (r * 2 + h) * 128;
#pragma unroll
                for (int p4 = 0; p4 < 4; p4++) {
                    const uint4 bq = wf[p4 * 32 + lane];
                    mma_bf16(acc[2 * p4][0], acc[2 * p4][1], acc[2 * p4][2], acc[2 * p4][3],
                             a0, a1, a2, a3, bq.x, bq.y);
                    mma_bf16(acc[2 * p4 + 1][0], acc[2 * p4 + 1][1],
                             acc[2 * p4 + 1][2], acc[2 * p4 + 1][3],
                             a0, a1, a2, a3, bq.z, bq.w);
                }
            }
        }

        // epilogue: 2x2 maxpool across quad rows via shfl_xor, bias+relu, bf16 store
        const int hh = lane >> 4;
        const int rr = lane & 3;
        const bool writer = ((lane & 12) == 0);
        const int qb = t * 32 + w * 4;
#pragma unroll
        for (int n = 0; n < 8; n++) {
            float v0 = acc[n][0], v1 = acc[n][1], v2 = acc[n][2], v3 = acc[n][3];
#pragma unroll
            for (int d = 4; d <= 8; d <<= 1) {
                v0 = fmaxf(v0, __shfl_xor_sync(0xffffffffu, v0, d));
                v1 = fmaxf(v1, __shfl_xor_sync(0xffffffffu, v1, d));
                v2 = fmaxf(v2, __shfl_xor_sync(0xffffffffu, v2, d));
                v3 = fmaxf(v3, __shfl_xor_sync(0xffffffffu, v3, d));
            }
            if (writer) {
                const int oc = n * 8 + 2 * rr;
                const float ba = sb2[oc], bb = sb2[oc + 1];
                *(uint32_t*)(outB + (qb + hh) * 64 + oc) =
                    packbf(fmaxf(v0 + ba, 0.f), fmaxf(v1 + bb, 0.f));
                *(uint32_t*)(outB + (qb + 2 + hh) * 64 + oc) =
                    packbf(fmaxf(v2 + ba, 0.f), fmaxf(v3 + bb, 0.f));
            }
        }
    }
}

// ---------------------------------------------------------------------------
// fc1 bf16 tensor-core with K-split: grid (16 Mblocks, 8 ksplits), 256 thr.
// ---------------------------------------------------------------------------
__global__ void __launch_bounds__(256) fc1_part_kernel()
{
    const int tid = threadIdx.x;
    const int w = tid >> 5;
    const int lane = tid & 31;
    const int Mb = blockIdx.x;         // 0..15
    const int ks = blockIdx.y;         // 0..7
    const int m0 = Mb * 128 + w * 16;
    const int g = lane >> 2, c = lane & 3;

    float acc[16][4];
#pragma unroll
    for (int f = 0; f < 16; f++) {
        acc[f][0] = 0.f; acc[f][1] = 0.f; acc[f][2] = 0.f; acc[f][3] = 0.f;
    }

    const __nv_bfloat16* A0 = g_poolh + (size_t)(m0 + g) * 9216;
    const __nv_bfloat16* A1 = g_poolh + (size_t)(m0 + g + 8) * 9216;

    for (int step = 0; step < 72; step++) {
        const int k0 = ks * 1152 + step * 16;
        const uint32_t a0 = *(const uint32_t*)(A0 + k0 + 2 * c);
        const uint32_t a1 = *(const uint32_t*)(A1 + k0 + 2 * c);
        const uint32_t a2 = *(const uint32_t*)(A0 + k0 + 2 * c + 8);
        const uint32_t a3 = *(const uint32_t*)(A1 + k0 + 2 * c + 8);
        const uint4* wf = g_fc1wfrag + (size_t)(ks * 72 + step) * 256;
#pragma unroll
        for (int p4 = 0; p4 < 8; p4++) {
            const uint4 bq = wf[p4 * 32 + lane];
            mma_bf16(acc[2 * p4][0], acc[2 * p4][1], acc[2 * p4][2], acc[2 * p4][3],
                     a0, a1, a2, a3, bq.x, bq.y);
            mma_bf16(acc[2 * p4 + 1][0], acc[2 * p4 + 1][1],
                     acc[2 * p4 + 1][2], acc[2 * p4 + 1][3],
                     a0, a1, a2, a3, bq.z, bq.w);
        }
    }

    float* dst = g_part + (size_t)ks * BATCH * 128;
#pragma unroll
    for (int f = 0; f < 16; f++) {
        const int n0 = f * 8 + 2 * c;
        *(float2*)(dst + (size_t)(m0 + g) * 128 + n0) = make_float2(acc[f][0], acc[f][1]);
        *(float2*)(dst + (size_t)(m0 + g + 8) * 128 + n0) = make_float2(acc[f][2], acc[f][3]);
    }
}

// ---------------------------------------------------------------------------
// quantum kernel; wire w <-> bit (9-w).  Fuses the fc1 K-split reduce +
// bias + relu into the load phase.  Single-pass <Y_k> reduction.
// ---------------------------------------------------------------------------
__device__ __forceinline__ float2 cmul(float2 a, float2 b) {
    return make_float2(a.x * b.x - a.y * b.y, a.x * b.y + a.y * b.x);
}
__device__ __forceinline__ float2 cadd(float2 a, float2 b) {
    return make_float2(a.x + b.x, a.y + b.y);
}

__global__ void qsim_kernel(const float* __restrict__ fc1b,
                            const float* __restrict__ fc2w,
                            const float* __restrict__ fc2b,
                            const float* __restrict__ theta0,
                            const float* __restrict__ theta_rz,
                            const float* __restrict__ theta_ps,
                            const float* __restrict__ rot_p,
                            float* __restrict__ out)
{
    __shared__ float sh[128];
    __shared__ float sang[10];
    __shared__ float2 svec[10][2];
    __shared__ float2 psi[1024];
    __shared__ float sredk[8][10];
    __shared__ float sev[10];

    const int b = blockIdx.x;
    const int tid = threadIdx.x;
    const int wid = tid >> 5, lane = tid & 31;

    // fc1 K-split reduce + bias + relu (coalesced over tid per slice)
    if (tid < 128) {
        float s = 0.0f;
#pragma unroll
        for (int ks = 0; ks < 8; ks++)
            s += g_part[(size_t)ks * BATCH * 128 + (size_t)b * 128 + tid];
        sh[tid] = fmaxf(s + fc1b[tid], 0.0f);
    }
    __syncthreads();

    if (tid < 10) {
        float z = fc2b[tid];
        const float4* sh4 = (const float4*)sh;
        const float4* wr4 = (const float4*)(fc2w + tid * 128);
        for (int k = 0; k < 32; k++) {
            const float4 hv = sh4[k], wv = wr4[k];
            z += hv.x * wv.x + hv.y * wv.y + hv.z * wv.z + hv.w * wv.w;
        }
        const float a = 6.2831853071795864f / (1.0f + expf(-z));
        sang[tid] = a;

        float alpha = theta0[tid] + a;
        if (tid == 1) alpha += a;
        if (tid == 5) alpha -= 0.78539816339745f;
        const float c = cosf(0.5f * alpha);
        const float s = sinf(0.5f * alpha);
        float2 v0 = make_float2(c, 0.0f);
        float2 v1 = make_float2(0.0f, -s);

        if (tid == 2) {
            const float cy = cosf(0.5f * a), sy = sinf(0.5f * a);
            v0 = make_float2(cy * c, sy * s);
            v1 = make_float2(sy * c, -cy * s);
        } else if (tid == 3) {
            const float2 e = make_float2(cosf(0.5f * a), -sinf(0.5f * a));
            v0 = cmul(v0, e);
            v1 = cmul(v1, make_float2(e.x, -e.y));
        } else if (tid == 4) {
            v1 = make_float2(s, 0.0f);
        } else if (tid == 5) {
            const float r = 0.70710678118654752f;
            v1 = make_float2(s * r, -s * r);
        } else if (tid == 6) {
            const float t = theta_rz[0];
            const float2 e = make_float2(cosf(0.5f * t), -sinf(0.5f * t));
            v0 = cmul(v0, e);
            v1 = cmul(v1, make_float2(e.x, -e.y));
        } else if (tid == 7) {
            const float h0 = 0.5f * (c - s), h1 = 0.5f * (c + s);
            v0 = make_float2(h0, h0);
            v1 = make_float2(h1, -h1);
        }
        svec[tid][0] = v0;
        svec[tid][1] = v1;
    }
    __syncthreads();

    for (int i = tid; i < 1024; i += 256) {
        float2 p = svec[0][(i >> 9) & 1];
#pragma unroll
        for (int k = 1; k < 10; k++)
            p = cmul(p, svec[k][(i >> (9 - k)) & 1]);
        if (i & 512) p = make_float2(p.y, -p.x);
        psi[i] = p;
    }
    __syncthreads();

    for (int p = tid; p < 512; p += 256) {
        const int i0 = ((p & ~1) << 1) | (p & 1);
        if (i0 & 64) {
            const int i1 = i0 | 2;
            const float2 t0 = psi[i0], t1 = psi[i1];
            psi[i0] = make_float2(t1.y, -t1.x);
            psi[i1] = make_float2(-t0.y, t0.x);
        }
    }
    __syncthreads();

    for (int i = tid; i < 1024; i += 256) {
        if ((i & 192) == 128) {
            const int j = i ^ 192;
            const float2 t = psi[i]; psi[i] = psi[j]; psi[j] = t;
        }
    }
    __syncthreads();

    for (int i = tid; i < 1024; i += 256) {
        if ((i & 32) && ((i & 24) == 16)) {
            const int j = i ^ 24;
            const float2 t = psi[i]; psi[i] = psi[j]; psi[j] = t;
        }
    }
    __syncthreads();

    for (int p = tid; p < 512; p += 256) {
        if ((p & 18) == 18) {
            const int j = p | 512;
            const float2 t = psi[p]; psi[p] = psi[j]; psi[j] = t;
        }
    }
    __syncthreads();

    {
        const float tps = theta_ps[0];
        const float a7 = sang[7];
        const float2 e8 = make_float2(cosf(tps), sinf(tps));
        const float2 e7 = make_float2(cosf(a7), sinf(a7));
        for (int i = tid; i < 1024; i += 256) {
            float2 v = psi[i];
            if (i & 2) v = cmul(v, e8);
            if (i & 4) v = cmul(v, e7);
            psi[i] = v;
        }
    }
    __syncthreads();

    {
        const float phi = rot_p[0], th = rot_p[1], om = rot_p[2];
        const float c = cosf(0.5f * th), s = sinf(0.5f * th);
        const float hs = 0.5f * (phi + om), hd = 0.5f * (phi - om);
        const float2 m00 = make_float2(c * cosf(hs), -c * sinf(hs));
        const float2 m01 = make_float2(-s * cosf(hd), -s * sinf(hd));
        const float2 m10 = make_float2(s * cosf(hd), -s * sinf(hd));
        const float2 m11 = make_float2(c * cosf(hs), c * sinf(hs));
        for (int p = tid; p < 512; p += 256) {
            const int lo = p & 31;
            const int i0 = ((p - lo) << 1) | lo;
            const int i1 = i0 | 32;
            const float2 t0 = psi[i0], t1 = psi[i1];
            psi[i0] = cadd(cmul(m00, t0), cmul(m01, t1));
            psi[i1] = cadd(cmul(m10, t0), cmul(m11, t1));
        }
    }
    __syncthreads();

    {
        const float phi = sang[6], th = sang[7], om = sang[8];
        const float c = cosf(0.5f * th), s = sinf(0.5f * th);
        const float hs = 0.5f * (phi + om), hd = 0.5f * (phi - om);
        const float2 m00 = make_float2(c * cosf(hs), -c * sinf(hs));
        const float2 m01 = make_float2(-s * cosf(hd), -s * sinf(hd));
        const float2 m10 = make_float2(s * cosf(hd), -s * sinf(hd));
        const float2 m11 = make_float2(c * cosf(hs), c * sinf(hs));
        for (int p = tid; p < 512; p += 256) {
            const int lo = p & 15;
            const int i0 = ((p - lo) << 1) | lo;
            const int i1 = i0 | 16;
            const float2 t0 = psi[i0], t1 = psi[i1];
            psi[i0] = cadd(cmul(m00, t0), cmul(m01, t1));
            psi[i1] = cadd(cmul(m10, t0), cmul(m11, t1));
        }
    }
    __syncthreads();

    // single-pass expectations
    float ev[10];
#pragma unroll
    for (int k = 0; k < 10; k++) ev[k] = 0.0f;
#pragma unroll
    for (int ii = 0; ii < 4; ii++) {
        const int i = tid + ii * 256;
        const float2 a0 = psi[i];
#pragma unroll
        for (int k = 0; k < 10; k++) {
            const int bit = 512 >> k;
            if (!(i & bit)) {
                const float2 a1 = psi[i | bit];
                ev[k] += a0.x * a1.y - a0.y * a1.x;
            }
        }
    }
#pragma unroll
    for (int k = 0; k < 10; k++) {
#pragma unroll
        for (int off = 16; off > 0; off >>= 1)
            ev[k] += __shfl_down_sync(0xffffffffu, ev[k], off);
    }
    if (lane == 0) {
#pragma unroll
        for (int k = 0; k < 10; k++) sredk[wid][k] = ev[k];
    }
    __syncthreads();
    if (tid < 10) {
        float s = 0.0f;
#pragma unroll
        for (int w = 0; w < 8; w++) s += sredk[w][tid];
        sev[tid] = 2.0f * s;
    }
    __syncthreads();

    if (tid == 0) {
        float m = sev[0];
#pragma unroll
        for (int k = 1; k < 10; k++) m = fmaxf(m, sev[k]);
        float ssum = 0.0f;
#pragma unroll
        for (int k = 0; k < 10; k++) ssum += expf(sev[k] - m);
        const float l = logf(ssum);
#pragma unroll
        for (int k = 0; k < 10; k++)
            out[(size_t)b * 10 + k] = sev[k] - m - l;
    }
}

// ---------------------------------------------------------------------------
// launch
// ---------------------------------------------------------------------------
extern "C" void kernel_launch(void* const* d_in, const int* in_sizes, int n_in,
                              void* d_out, int out_size)
{
    const float* x        = (const float*)d_in[0];
    const float* conv1_w  = (const float*)d_in[1];
    const float* conv1_b  = (const float*)d_in[2];
    const float* conv2_w  = (const float*)d_in[3];
    const float* conv2_b  = (const float*)d_in[4];
    const float* fc1_w    = (const float*)d_in[5];
    const float* fc1_b    = (const float*)d_in[6];
    const float* fc2_w    = (const float*)d_in[7];
    const float* fc2_b    = (const float*)d_in[8];
    const float* theta0   = (const float*)d_in[9];
    const float* theta_rz = (const float*)d_in[10];
    const float* theta_ps = (const float*)d_in[11];
    const float* rot_p    = (const float*)d_in[12];
    float* out = (float*)d_out;

    // sIn 45968 + sx 3136 + sw1 1152 + sb1 128 + sb2 256 = 50640 B
    const int conv_smem = 50640;
    cudaFuncSetAttribute(conv12_kernel, cudaFuncAttributeMaxDynamicSharedMemorySize,
                         conv_smem);

    prep_wfrag_kernel<<<18, 128>>>(conv2_w);
    prep_fc1w_kernel<<<(128 * 9216) / 256, 256>>>(fc1_w);
    prep_fc1frag_kernel<<<576, 256>>>();
    conv12_kernel<<<BATCH, 256, conv_smem>>>(x, conv1_w, conv1_b, conv2_b);
    fc1_part_kernel<<<dim3(16, 8), 256>>>();
    qsim_kernel<<<BATCH, 256>>>(fc1_b, fc2_w, fc2_b, theta0, theta_rz, theta_ps, rot_p, out);
}